// round 13
// baseline (speedup 1.0000x reference)
#include <cuda_runtime.h>

// xg scratch: [B=32][T=2048][4H=1024] fp32 = 256 MB
__device__ float g_xg[32ull * 2048ull * 1024ull];

// ---------------- f32x2 helpers (sm_103a packed fp32) ----------------
__device__ __forceinline__ void fma2(unsigned long long &acc,
                                     unsigned long long a,
                                     unsigned long long b) {
    asm("fma.rn.f32x2 %0, %1, %2, %0;" : "+l"(acc) : "l"(a), "l"(b));
}
__device__ __forceinline__ unsigned long long splat2(float x) {
    unsigned long long r;
    unsigned xu = __float_as_uint(x);
    asm("mov.b64 %0, {%1, %1};" : "=l"(r) : "r"(xu));
    return r;
}
__device__ __forceinline__ float hadd2(unsigned long long v) {
    float lo, hi;
    asm("mov.b64 {%0, %1}, %2;" : "=f"(lo), "=f"(hi) : "l"(v));
    return lo + hi;
}
__device__ __forceinline__ unsigned long long add2(unsigned long long a,
                                                   unsigned long long b) {
    unsigned long long r;
    asm("add.rn.f32x2 %0, %1, %2;" : "=l"(r) : "l"(a), "l"(b));
    return r;
}
__device__ __forceinline__ float sigf(float x) {
    return __fdividef(1.f, 1.f + __expf(-x));
}
__device__ __forceinline__ float tanhf_fast(float x) {
    return __fdividef(2.f, 1.f + __expf(-2.f * x)) - 1.f;
}
__device__ __forceinline__ unsigned smem_u32(const void* p) {
    return (unsigned)__cvta_generic_to_shared(p);
}

// mbarrier primitives
__device__ __forceinline__ void mbar_init(unsigned mbar, unsigned cnt) {
    asm volatile("mbarrier.init.shared.b64 [%0], %1;" :: "r"(mbar), "r"(cnt) : "memory");
}
__device__ __forceinline__ void mbar_arm_tx(unsigned mbar, unsigned bytes) {
    asm volatile("mbarrier.arrive.expect_tx.shared.b64 _, [%0], %1;"
                 :: "r"(mbar), "r"(bytes) : "memory");
}
__device__ __forceinline__ void mbar_wait(unsigned mbar, unsigned parity) {
    unsigned done;
    asm volatile(
        "{\n\t.reg .pred p;\n\t"
        "mbarrier.try_wait.parity.acquire.cta.shared::cta.b64 p, [%1], %2;\n\t"
        "selp.b32 %0, 1, 0, p;\n\t}"
        : "=r"(done) : "r"(mbar), "r"(parity) : "memory");
    while (!done) {
        asm volatile(
            "{\n\t.reg .pred p;\n\t"
            "mbarrier.try_wait.parity.acquire.cta.shared::cta.b64 p, [%1], %2, 0x989680;\n\t"
            "selp.b32 %0, 1, 0, p;\n\t}"
            : "=r"(done) : "r"(mbar), "r"(parity) : "memory");
    }
}
// 16B remote store + tx-signal (remote addresses pre-mapped)
__device__ __forceinline__ void st_async_v4_pre(unsigned ra, unsigned rb,
                                                float x, float y, float z, float w) {
    asm volatile(
        "st.async.shared::cluster.mbarrier::complete_tx::bytes.v4.b32 "
        "[%0], {%2, %3, %4, %5}, [%1];"
        :: "r"(ra), "r"(rb),
           "r"(__float_as_uint(x)), "r"(__float_as_uint(y)),
           "r"(__float_as_uint(z)), "r"(__float_as_uint(w)) : "memory");
}

// =====================================================================
// Phase 1: xg[m][g] = relu(x)[m][:] . W_ih[g][:] + b_ih[g] + b_hh[g]
// (unchanged — FMA-bound, not the bottleneck)
// =====================================================================
__global__ __launch_bounds__(256, 2) void p1_gemm(
    const float* __restrict__ x, const float* __restrict__ Wih,
    const float* __restrict__ bih, const float* __restrict__ bhh)
{
    __shared__ __align__(16) float Asm[16][132];  // [k][m]
    __shared__ __align__(16) float Wsm[16][132];  // [k][g]

    const int t  = threadIdx.x;
    const int tx = t & 15, ty = t >> 4;
    const int mb = blockIdx.y * 128;
    const int gb = blockIdx.x * 128;

    unsigned long long acc[4][8];
    #pragma unroll
    for (int p = 0; p < 4; p++)
        #pragma unroll
        for (int g = 0; g < 8; g++) acc[p][g] = 0ull;

    for (int kb = 0; kb < 256; kb += 16) {
        #pragma unroll
        for (int i = 0; i < 2; i++) {
            int idx = t + i * 256;
            int m   = idx >> 2;
            int kc  = (idx & 3) << 2;
            float4 av = *(const float4*)(x + (size_t)(mb + m) * 256 + kb + kc);
            Asm[kc + 0][m] = fmaxf(av.x, 0.f);
            Asm[kc + 1][m] = fmaxf(av.y, 0.f);
            Asm[kc + 2][m] = fmaxf(av.z, 0.f);
            Asm[kc + 3][m] = fmaxf(av.w, 0.f);
            float4 wv = *(const float4*)(Wih + (size_t)(gb + m) * 256 + kb + kc);
            Wsm[kc + 0][m] = wv.x;
            Wsm[kc + 1][m] = wv.y;
            Wsm[kc + 2][m] = wv.z;
            Wsm[kc + 3][m] = wv.w;
        }
        __syncthreads();
        #pragma unroll
        for (int k = 0; k < 16; k++) {
            ulonglong2 a01 = *(const ulonglong2*)&Asm[k][ty * 8];
            ulonglong2 a23 = *(const ulonglong2*)&Asm[k][ty * 8 + 4];
            float4 w0 = *(const float4*)&Wsm[k][tx * 8];
            float4 w1 = *(const float4*)&Wsm[k][tx * 8 + 4];
            float wf[8] = {w0.x, w0.y, w0.z, w0.w, w1.x, w1.y, w1.z, w1.w};
            #pragma unroll
            for (int g = 0; g < 8; g++) {
                unsigned long long ws = splat2(wf[g]);
                fma2(acc[0][g], a01.x, ws);
                fma2(acc[1][g], a01.y, ws);
                fma2(acc[2][g], a23.x, ws);
                fma2(acc[3][g], a23.y, ws);
            }
        }
        __syncthreads();
    }

    float bs[8];
    {
        const float4* bi = (const float4*)(bih + gb + tx * 8);
        const float4* bh = (const float4*)(bhh + gb + tx * 8);
        float4 b0 = bi[0], b1 = bi[1], c0 = bh[0], c1 = bh[1];
        bs[0] = b0.x + c0.x; bs[1] = b0.y + c0.y; bs[2] = b0.z + c0.z; bs[3] = b0.w + c0.w;
        bs[4] = b1.x + c1.x; bs[5] = b1.y + c1.y; bs[6] = b1.z + c1.z; bs[7] = b1.w + c1.w;
    }
    #pragma unroll
    for (int p = 0; p < 4; p++) {
        float lo[8], hi[8];
        #pragma unroll
        for (int g = 0; g < 8; g++) {
            float l, h;
            asm("mov.b64 {%0, %1}, %2;" : "=f"(l), "=f"(h) : "l"(acc[p][g]));
            lo[g] = l + bs[g];
            hi[g] = h + bs[g];
        }
        size_t m0 = (size_t)(mb + ty * 8 + 2 * p);
        float* r0 = g_xg + m0 * 1024 + gb + tx * 8;
        float* r1 = r0 + 1024;
        *(float4*)(r0)     = make_float4(lo[0], lo[1], lo[2], lo[3]);
        *(float4*)(r0 + 4) = make_float4(lo[4], lo[5], lo[6], lo[7]);
        *(float4*)(r1)     = make_float4(hi[0], hi[1], hi[2], hi[3]);
        *(float4*)(r1 + 4) = make_float4(hi[4], hi[5], hi[6], hi[7]);
    }
}

// =====================================================================
// Phase 2: warp-autonomous recurrence. 16 clusters x 8 CTAs, cluster c
// handles batches {2c,2c+1}. Row remap v = j4*4 + gt so each WARP owns
// 4 h-indices end-to-end (matvec, reduce, activate, update, send) with
// shfl-only data movement. NO __syncthreads in the loop; warps couple
// only through the per-phase mbarrier (st.async tx accounting).
// Thread (t): v = t>>1 (0..127), kh = t&1; j4 = v>>2; gt = v&3.
// Gate row G = gt*256 + rank*32 + j4; weights [kh*128..+128) in regs.
// =====================================================================
__global__ __launch_bounds__(256, 1) __cluster_dims__(8, 1, 1)
void p2_lstm(const float* __restrict__ Whh, float* __restrict__ out)
{
    __shared__ __align__(16) float hbuf[2][2][256];   // [buf][batch][k]
    __shared__ __align__(16) float ring[4][256];      // xg [slot][b*128+gt*32+j]
    __shared__ __align__(8)  unsigned long long barr[2];

    unsigned rank;
    asm("mov.u32 %0, %%cluster_ctarank;" : "=r"(rank));
    const int t    = threadIdx.x;
    const int lane = t & 31;
    const int w    = t >> 5;
    const int v    = t >> 1;
    const int kh   = t & 1;
    const int j4   = v >> 2;
    const int gt   = v & 3;
    const int G    = gt * 256 + (int)rank * 32 + j4;
    const int b0   = (blockIdx.x >> 3) * 2;

    // persistent weights: 64 x f32x2 (k = kh*128 + 2i)
    unsigned long long w2[64];
    {
        const unsigned long long* wp =
            (const unsigned long long*)(Whh + (size_t)G * 256 + kh * 128);
        #pragma unroll
        for (int i = 0; i < 64; i++) w2[i] = wp[i];
    }

    for (int i = t; i < 1024; i += 256) ((float*)hbuf)[i] = 0.f;

    // xg ring loader: thread t covers (b=t>>7, g2=(t>>5)&3, j2=t&31)
    const float* xg_ld = g_xg
        + (size_t)(b0 + (t >> 7)) * 2048 * 1024
        + (size_t)(((t >> 5) & 3) * 256 + (int)rank * 32 + (t & 31));
    ring[0][t] = xg_ld[0];
    ring[1][t] = xg_ld[1024];
    float pend = xg_ld[2 * 1024];

    const unsigned bar0 = smem_u32(&barr[0]);
    const unsigned bar1 = smem_u32(&barr[1]);
    if (t == 0) { mbar_init(bar0, 1); mbar_init(bar1, 1); }

    // per-thread remote constants (sender role, lanes 0..15)
    const int drank = lane & 7;
    const int bsel  = (lane >> 3) & 1;          // 0: batch A payload, 1: batch B
    unsigned rbar0, rbar1, rdst0;
    {
        unsigned dloc0 = smem_u32(&hbuf[0][bsel][(int)rank * 32 + 4 * w]);
        asm("mapa.shared::cluster.u32 %0, %1, %2;" : "=r"(rbar0) : "r"(bar0), "r"(drank));
        asm("mapa.shared::cluster.u32 %0, %1, %2;" : "=r"(rbar1) : "r"(bar1), "r"(drank));
        asm("mapa.shared::cluster.u32 %0, %1, %2;" : "=r"(rdst0) : "r"(dloc0), "r"(drank));
    }

    __syncthreads();
    asm volatile("barrier.cluster.arrive.aligned;" ::: "memory");
    asm volatile("barrier.cluster.wait.aligned;"   ::: "memory");
    if (t == 0) { mbar_arm_tx(bar0, 2048); mbar_arm_tx(bar1, 2048); }

    // updater role (lanes 0..7): batch ub = (lane>>2)&1, h-index 4w+(lane&3)
    const int ub  = (lane >> 2) & 1;
    const int uj4 = 4 * w + (lane & 3);
    float* outp = out + (size_t)(b0 + ub) * 2048 * 256 + (int)rank * 32 + uj4;
    const int xoff = ub * 128 + uj4;            // + gt*32 per gate
    float c_state = 0.f;
    unsigned ph0 = 0, ph1 = 0;
    const int gbase = (lane & 3) << 3;          // gather base lane

    for (int s = 0; s < 2048; s++) {
        const int rb = s & 1;
        const int wb = rb ^ 1;

        if (s > 0) {
            if (rb) { mbar_wait(bar1, ph1); ph1 ^= 1; if (t == 0) mbar_arm_tx(bar1, 2048); }
            else    { mbar_wait(bar0, ph0); ph0 ^= 1; if (t == 0) mbar_arm_tx(bar0, 2048); }
        }

        // xg for this step (off the critical tail); ring slot s&3 is old
        const float* xr = &ring[s & 3][xoff];
        float xg0 = xr[0], xg1 = xr[32], xg2 = xr[64], xg3 = xr[96];

        // ring pipeline: store s+2 (loaded last iter), start load for s+3
        ring[(s + 2) & 3][t] = pend;
        {
            int ps = s + 3; if (ps > 2047) ps = 2047;
            pend = xg_ld[(size_t)ps * 1024];
        }

        // ---- matvec: both batches, kh half, 4 accs each ----
        unsigned long long aA0 = 0, aA1 = 0, aA2 = 0, aA3 = 0;
        unsigned long long aB0 = 0, aB1 = 0, aB2 = 0, aB3 = 0;
        {
            const ulonglong2* hpA = (const ulonglong2*)&hbuf[rb][0][kh << 7];
            const ulonglong2* hpB = (const ulonglong2*)&hbuf[rb][1][kh << 7];
            #pragma unroll
            for (int i = 0; i < 32; i += 2) {
                ulonglong2 ha0 = hpA[i], ha1 = hpA[i + 1];
                ulonglong2 hb0 = hpB[i], hb1 = hpB[i + 1];
                fma2(aA0, w2[2 * i],     ha0.x);
                fma2(aA1, w2[2 * i + 1], ha0.y);
                fma2(aA2, w2[2 * i + 2], ha1.x);
                fma2(aA3, w2[2 * i + 3], ha1.y);
                fma2(aB0, w2[2 * i],     hb0.x);
                fma2(aB1, w2[2 * i + 1], hb0.y);
                fma2(aB2, w2[2 * i + 2], hb1.x);
                fma2(aB3, w2[2 * i + 3], hb1.y);
            }
        }
        float pA = hadd2(add2(add2(aA0, aA1), add2(aA2, aA3)));
        float pB = hadd2(add2(add2(aB0, aB1), add2(aB2, aB3)));

        // kh-combine within the thread pair (lanes l, l^1 share row v)
        float fullA = pA + __shfl_xor_sync(0xffffffffu, pA, 1);
        float fullB = pB + __shfl_xor_sync(0xffffffffu, pB, 1);

        // gate gather: gate (j4=4w+p, gt) lives at lanes 8p+2gt{,+1}
        float gAi = __shfl_sync(0xffffffffu, fullA, gbase);
        float gAf = __shfl_sync(0xffffffffu, fullA, gbase + 2);
        float gAg = __shfl_sync(0xffffffffu, fullA, gbase + 4);
        float gAo = __shfl_sync(0xffffffffu, fullA, gbase + 6);
        float gBi = __shfl_sync(0xffffffffu, fullB, gbase);
        float gBf = __shfl_sync(0xffffffffu, fullB, gbase + 2);
        float gBg = __shfl_sync(0xffffffffu, fullB, gbase + 4);
        float gBo = __shfl_sync(0xffffffffu, fullB, gbase + 6);

        // update (meaningful on lanes 0-7; uniform execution, no divergence)
        float gi = (ub ? gBi : gAi) + xg0;
        float gf = (ub ? gBf : gAf) + xg1;
        float gg = (ub ? gBg : gAg) + xg2;
        float go = (ub ? gBo : gAo) + xg3;
        float iv = sigf(gi), fv = sigf(gf);
        float gv = tanhf_fast(gg), ov = sigf(go);
        c_state = fv * c_state + iv * gv;
        float h = ov * tanhf_fast(c_state);

        // gather the 4-float h payloads (A from lanes 0-3, B from 4-7)
        float ax = __shfl_sync(0xffffffffu, h, 0);
        float ay = __shfl_sync(0xffffffffu, h, 1);
        float az = __shfl_sync(0xffffffffu, h, 2);
        float aw = __shfl_sync(0xffffffffu, h, 3);
        float bx = __shfl_sync(0xffffffffu, h, 4);
        float by = __shfl_sync(0xffffffffu, h, 5);
        float bz = __shfl_sync(0xffffffffu, h, 6);
        float bw = __shfl_sync(0xffffffffu, h, 7);

        // parallel sends: lanes 0-7 carry batch A, lanes 8-15 batch B,
        // destination rank = lane&7. One st.async per lane.
        if (s < 2047 && lane < 16) {
            float dx = bsel ? bx : ax;
            float dy = bsel ? by : ay;
            float dz = bsel ? bz : az;
            float dw = bsel ? bw : aw;
            unsigned ra = rdst0 + (unsigned)(wb * 2048);
            unsigned rbb = wb ? rbar1 : rbar0;
            st_async_v4_pre(ra, rbb, dx, dy, dz, dw);
        }
        if (lane < 8) outp[(size_t)s * 256] = h;
    }

    asm volatile("barrier.cluster.arrive.aligned;" ::: "memory");
    asm volatile("barrier.cluster.wait.aligned;"   ::: "memory");
}

// =====================================================================
extern "C" void kernel_launch(void* const* d_in, const int* in_sizes, int n_in,
                              void* d_out, int out_size) {
    (void)in_sizes; (void)n_in; (void)out_size;
    const float* x   = (const float*)d_in[0];
    const float* Wih = (const float*)d_in[1];
    const float* Whh = (const float*)d_in[2];
    const float* bih = (const float*)d_in[3];
    const float* bhh = (const float*)d_in[4];
    float* out = (float*)d_out;

    dim3 g1(8, 512);
    p1_gemm<<<g1, 256>>>(x, Wih, bih, bhh);
    p2_lstm<<<128, 256>>>(Whh, out);   // 16 clusters of 8 CTAs
}

// round 15
// speedup vs baseline: 1.4244x; 1.4244x over previous
#include <cuda_runtime.h>

// xg scratch: [B=32][T=2048][4H=1024] fp32 = 256 MB
__device__ float g_xg[32ull * 2048ull * 1024ull];

// ---------------- f32x2 helpers (sm_103a packed fp32) ----------------
__device__ __forceinline__ void fma2(unsigned long long &acc,
                                     unsigned long long a,
                                     unsigned long long b) {
    asm("fma.rn.f32x2 %0, %1, %2, %0;" : "+l"(acc) : "l"(a), "l"(b));
}
__device__ __forceinline__ unsigned long long splat2(float x) {
    unsigned long long r;
    unsigned xu = __float_as_uint(x);
    asm("mov.b64 %0, {%1, %1};" : "=l"(r) : "r"(xu));
    return r;
}
__device__ __forceinline__ float hadd2(unsigned long long v) {
    float lo, hi;
    asm("mov.b64 {%0, %1}, %2;" : "=f"(lo), "=f"(hi) : "l"(v));
    return lo + hi;
}
__device__ __forceinline__ float sigf(float x) {
    return __fdividef(1.f, 1.f + __expf(-x));
}
__device__ __forceinline__ float tanhf_fast(float x) {
    return __fdividef(2.f, 1.f + __expf(-2.f * x)) - 1.f;
}
__device__ __forceinline__ unsigned smem_u32(const void* p) {
    return (unsigned)__cvta_generic_to_shared(p);
}

// mbarrier primitives
__device__ __forceinline__ void mbar_init(unsigned mbar, unsigned cnt) {
    asm volatile("mbarrier.init.shared.b64 [%0], %1;" :: "r"(mbar), "r"(cnt) : "memory");
}
__device__ __forceinline__ void mbar_arm_tx(unsigned mbar, unsigned bytes) {
    asm volatile("mbarrier.arrive.expect_tx.shared.b64 _, [%0], %1;"
                 :: "r"(mbar), "r"(bytes) : "memory");
}
__device__ __forceinline__ void mbar_wait(unsigned mbar, unsigned parity) {
    unsigned done;
    asm volatile(
        "{\n\t.reg .pred p;\n\t"
        "mbarrier.try_wait.parity.acquire.cta.shared::cta.b64 p, [%1], %2;\n\t"
        "selp.b32 %0, 1, 0, p;\n\t}"
        : "=r"(done) : "r"(mbar), "r"(parity) : "memory");
    while (!done) {
        asm volatile(
            "{\n\t.reg .pred p;\n\t"
            "mbarrier.try_wait.parity.acquire.cta.shared::cta.b64 p, [%1], %2, 0x989680;\n\t"
            "selp.b32 %0, 1, 0, p;\n\t}"
            : "=r"(done) : "r"(mbar), "r"(parity) : "memory");
    }
}
// 16B remote store + tx-signal (remote addresses pre-mapped per lane)
__device__ __forceinline__ void st_async_v4_pre(unsigned ra, unsigned rb,
                                                float x, float y, float z, float w) {
    asm volatile(
        "st.async.shared::cluster.mbarrier::complete_tx::bytes.v4.b32 "
        "[%0], {%2, %3, %4, %5}, [%1];"
        :: "r"(ra), "r"(rb),
           "r"(__float_as_uint(x)), "r"(__float_as_uint(y)),
           "r"(__float_as_uint(z)), "r"(__float_as_uint(w)) : "memory");
}

// =====================================================================
// Phase 1: xg[m][g] = relu(x)[m][:] . W_ih[g][:] + b_ih[g] + b_hh[g]
// (unchanged — FMA-bound, not the bottleneck)
// =====================================================================
__global__ __launch_bounds__(256, 2) void p1_gemm(
    const float* __restrict__ x, const float* __restrict__ Wih,
    const float* __restrict__ bih, const float* __restrict__ bhh)
{
    __shared__ __align__(16) float Asm[16][132];  // [k][m]
    __shared__ __align__(16) float Wsm[16][132];  // [k][g]

    const int t  = threadIdx.x;
    const int tx = t & 15, ty = t >> 4;
    const int mb = blockIdx.y * 128;
    const int gb = blockIdx.x * 128;

    unsigned long long acc[4][8];
    #pragma unroll
    for (int p = 0; p < 4; p++)
        #pragma unroll
        for (int g = 0; g < 8; g++) acc[p][g] = 0ull;

    for (int kb = 0; kb < 256; kb += 16) {
        #pragma unroll
        for (int i = 0; i < 2; i++) {
            int idx = t + i * 256;
            int m   = idx >> 2;
            int kc  = (idx & 3) << 2;
            float4 av = *(const float4*)(x + (size_t)(mb + m) * 256 + kb + kc);
            Asm[kc + 0][m] = fmaxf(av.x, 0.f);
            Asm[kc + 1][m] = fmaxf(av.y, 0.f);
            Asm[kc + 2][m] = fmaxf(av.z, 0.f);
            Asm[kc + 3][m] = fmaxf(av.w, 0.f);
            float4 wv = *(const float4*)(Wih + (size_t)(gb + m) * 256 + kb + kc);
            Wsm[kc + 0][m] = wv.x;
            Wsm[kc + 1][m] = wv.y;
            Wsm[kc + 2][m] = wv.z;
            Wsm[kc + 3][m] = wv.w;
        }
        __syncthreads();
        #pragma unroll
        for (int k = 0; k < 16; k++) {
            ulonglong2 a01 = *(const ulonglong2*)&Asm[k][ty * 8];
            ulonglong2 a23 = *(const ulonglong2*)&Asm[k][ty * 8 + 4];
            float4 w0 = *(const float4*)&Wsm[k][tx * 8];
            float4 w1 = *(const float4*)&Wsm[k][tx * 8 + 4];
            float wf[8] = {w0.x, w0.y, w0.z, w0.w, w1.x, w1.y, w1.z, w1.w};
            #pragma unroll
            for (int g = 0; g < 8; g++) {
                unsigned long long ws = splat2(wf[g]);
                fma2(acc[0][g], a01.x, ws);
                fma2(acc[1][g], a01.y, ws);
                fma2(acc[2][g], a23.x, ws);
                fma2(acc[3][g], a23.y, ws);
            }
        }
        __syncthreads();
    }

    float bs[8];
    {
        const float4* bi = (const float4*)(bih + gb + tx * 8);
        const float4* bh = (const float4*)(bhh + gb + tx * 8);
        float4 b0 = bi[0], b1 = bi[1], c0 = bh[0], c1 = bh[1];
        bs[0] = b0.x + c0.x; bs[1] = b0.y + c0.y; bs[2] = b0.z + c0.z; bs[3] = b0.w + c0.w;
        bs[4] = b1.x + c1.x; bs[5] = b1.y + c1.y; bs[6] = b1.z + c1.z; bs[7] = b1.w + c1.w;
    }
    #pragma unroll
    for (int p = 0; p < 4; p++) {
        float lo[8], hi[8];
        #pragma unroll
        for (int g = 0; g < 8; g++) {
            float l, h;
            asm("mov.b64 {%0, %1}, %2;" : "=f"(l), "=f"(h) : "l"(acc[p][g]));
            lo[g] = l + bs[g];
            hi[g] = h + bs[g];
        }
        size_t m0 = (size_t)(mb + ty * 8 + 2 * p);
        float* r0 = g_xg + m0 * 1024 + gb + tx * 8;
        float* r1 = r0 + 1024;
        *(float4*)(r0)     = make_float4(lo[0], lo[1], lo[2], lo[3]);
        *(float4*)(r0 + 4) = make_float4(lo[4], lo[5], lo[6], lo[7]);
        *(float4*)(r1)     = make_float4(hi[0], hi[1], hi[2], hi[3]);
        *(float4*)(r1 + 4) = make_float4(hi[4], hi[5], hi[6], hi[7]);
    }
}

// =====================================================================
// Phase 2: recurrence (R4 chassis). 16 clusters x 8 CTAs; cluster c
// handles batches {2c, 2c+1}. CTA rank r owns h-indices [32r,32r+32).
// h buffer rank-major: h_lin[buf][r*64 + b*32 + j].
// R14 deltas vs R4: (1) sends parallelized over all 64 update threads
// (2 full-warp st.async.v4 instead of 16 threads x 8 serial);
// (2) ring STS + xg LDG + xg4 LDS hoisted before the mbarrier wait;
// (3) output STG moved after the sends.
// =====================================================================
__global__ __launch_bounds__(256, 1) __cluster_dims__(8, 1, 1)
void p2_lstm(const float* __restrict__ Whh, float* __restrict__ out)
{
    __shared__ __align__(16) float h_lin[2][512];     // [buf][r*64+b*32+j]
    __shared__ __align__(16) float ring[4][256];      // xg [slot][b*128+gt*32+j]
    __shared__ __align__(8)  float red_sm[2][128][2]; // [kh][row][batch]
    __shared__ __align__(8)  unsigned long long barr[2];

    unsigned rank;
    asm("mov.u32 %0, %%cluster_ctarank;" : "=r"(rank));
    const int t   = threadIdx.x;
    const int row = t & 127;
    const int kh  = t >> 7;
    const int gt  = row >> 5;
    const int j   = row & 31;
    const int G   = gt * 256 + (int)rank * 32 + j;   // global gate row
    const int b0  = (blockIdx.x >> 3) * 2;

    // persistent weights: 64 x f32x2 in registers (k-linear over kh half)
    unsigned long long w2[64];
    {
        const unsigned long long* wp =
            (const unsigned long long*)(Whh + (size_t)G * 256 + kh * 128);
        #pragma unroll
        for (int i = 0; i < 64; i++) w2[i] = wp[i];
    }

    for (int i = t; i < 1024; i += 256) ((float*)h_lin)[i] = 0.f;

    // xg ring loader: thread t covers (b=t>>7, g2=(t>>5)&3, j2=t&31)
    const float* xg_ld = g_xg
        + (size_t)(b0 + (t >> 7)) * 2048 * 1024
        + (size_t)(((t >> 5) & 3) * 256 + (int)rank * 32 + (t & 31));
    ring[0][t] = xg_ld[0];
    ring[1][t] = xg_ld[1024];
    float pend = xg_ld[2 * 1024];

    const unsigned anchor = smem_u32(&h_lin[0][0]);
    const unsigned bar0 = smem_u32(&barr[0]);
    const unsigned bar1 = smem_u32(&barr[1]);
    if (t == 0) { mbar_init(bar0, 1); mbar_init(bar1, 1); }

    // ---- per-thread sender constants (update threads t<64) ----
    const int ub = t >> 5, uj = t & 31;   // batch, h-lane (t<64)
    const int qb = uj & ~3;               // quad base lane
    const int d0 = 2 * (uj & 3);          // two destination ranks
    const int d1 = d0 + 1;
    unsigned rb0m, rb1m;
    asm("mapa.shared::cluster.u32 %0, %1, %2;" : "=r"(rb0m) : "r"(anchor), "r"(d0));
    asm("mapa.shared::cluster.u32 %0, %1, %2;" : "=r"(rb1m) : "r"(anchor), "r"(d1));
    const unsigned hdelta0 = smem_u32(&h_lin[0][(int)rank * 64 + ub * 32 + qb]) - anchor;
    const unsigned hdelta1 = hdelta0 + 2048;      // h_lin[1] is +512 floats
    const unsigned bdelta0 = bar0 - anchor;
    const unsigned bdelta1 = bar1 - anchor;

    __syncthreads();
    asm volatile("barrier.cluster.arrive.aligned;" ::: "memory");
    asm volatile("barrier.cluster.wait.aligned;"   ::: "memory");
    if (t == 0) { mbar_arm_tx(bar0, 2048); mbar_arm_tx(bar1, 2048); }

    float c_state = 0.f;
    unsigned ph0 = 0, ph1 = 0;
    float* out_p = out + (size_t)(b0 + ub) * 2048 * 256 + (int)rank * 32 + uj;

    for (int s = 0; s < 2048; s++) {
        const int rb = s & 1;
        const int wb = rb ^ 1;

        // ---- pre-wait independent work (overlaps the mbarrier wait) ----
        ring[(s + 2) & 3][t] = pend;           // store step s+2 (loaded last iter)
        {
            int ps = s + 3; if (ps > 2047) ps = 2047;
            pend = xg_ld[(size_t)ps * 1024];   // start load for step s+3
        }
        float xg4[4];
        if (t < 64) {                          // this step's xg (slot written at s-2)
            const float* xp = &ring[s & 3][ub * 128 + uj];
            xg4[0] = xp[0]; xg4[1] = xp[32]; xg4[2] = xp[64]; xg4[3] = xp[96];
        }

        if (s > 0) {
            if (rb) { mbar_wait(bar1, ph1); ph1 ^= 1; if (t == 0) mbar_arm_tx(bar1, 2048); }
            else    { mbar_wait(bar0, ph0); ph0 ^= 1; if (t == 0) mbar_arm_tx(bar0, 2048); }
        }

        // ---- matvec: 2 batches x 128-k half, rank-major chunks ----
        unsigned long long a0a = 0ull, a0b = 0ull, a1a = 0ull, a1b = 0ull;
        #pragma unroll
        for (int c = 0; c < 4; c++) {
            const ulonglong2* hp0 =
                (const ulonglong2*)&h_lin[rb][(kh * 4 + c) * 64];
            const ulonglong2* hp1 =
                (const ulonglong2*)&h_lin[rb][(kh * 4 + c) * 64 + 32];
            #pragma unroll
            for (int q = 0; q < 8; q++) {
                ulonglong2 hv0 = hp0[q];
                ulonglong2 hv1 = hp1[q];
                int wi = c * 16 + 2 * q;
                fma2(a0a, w2[wi],     hv0.x);
                fma2(a0b, w2[wi + 1], hv0.y);
                fma2(a1a, w2[wi],     hv1.x);
                fma2(a1b, w2[wi + 1], hv1.y);
            }
        }
        red_sm[kh][row][0] = hadd2(a0a) + hadd2(a0b);
        red_sm[kh][row][1] = hadd2(a1a) + hadd2(a1b);
        __syncthreads();   // orders h_lin[rb] reads + red/ring writes

        // ---- fused activation + c/h update (64 threads, 2 full warps) ----
        if (t < 64) {
            float gi = red_sm[0][      uj][ub] + red_sm[1][      uj][ub] + xg4[0];
            float gf = red_sm[0][ 32 + uj][ub] + red_sm[1][ 32 + uj][ub] + xg4[1];
            float gg = red_sm[0][ 64 + uj][ub] + red_sm[1][ 64 + uj][ub] + xg4[2];
            float go = red_sm[0][ 96 + uj][ub] + red_sm[1][ 96 + uj][ub] + xg4[3];
            float iv = sigf(gi);
            float fv = sigf(gf);
            float gv = tanhf_fast(gg);
            float ov = sigf(go);
            c_state = fv * c_state + iv * gv;
            float h = ov * tanhf_fast(c_state);

            if (s < 2047) {
                // gather this lane's quad (4 consecutive h of own batch/warp)
                float p0 = __shfl_sync(0xffffffffu, h, qb);
                float p1 = __shfl_sync(0xffffffffu, h, qb + 1);
                float p2 = __shfl_sync(0xffffffffu, h, qb + 2);
                float p3 = __shfl_sync(0xffffffffu, h, qb + 3);
                unsigned hd = wb ? hdelta1 : hdelta0;
                unsigned bd = wb ? bdelta1 : bdelta0;
                // two sends per thread -> 128 sends total, fully warp-parallel
                st_async_v4_pre(rb0m + hd, rb0m + bd, p0, p1, p2, p3);
                st_async_v4_pre(rb1m + hd, rb1m + bd, p0, p1, p2, p3);
            }
            out_p[(size_t)s * 256] = h;   // after sends: off the critical path
        }
    }

    asm volatile("barrier.cluster.arrive.aligned;" ::: "memory");
    asm volatile("barrier.cluster.wait.aligned;"   ::: "memory");
}

// =====================================================================
extern "C" void kernel_launch(void* const* d_in, const int* in_sizes, int n_in,
                              void* d_out, int out_size) {
    (void)in_sizes; (void)n_in; (void)out_size;
    const float* x   = (const float*)d_in[0];
    const float* Wih = (const float*)d_in[1];
    const float* Whh = (const float*)d_in[2];
    const float* bih = (const float*)d_in[3];
    const float* bhh = (const float*)d_in[4];
    float* out = (float*)d_out;

    dim3 g1(8, 512);
    p1_gemm<<<g1, 256>>>(x, Wih, bih, bhh);
    p2_lstm<<<128, 256>>>(Whh, out);   // 16 clusters of 8 CTAs
}

// round 16
// speedup vs baseline: 1.5731x; 1.1044x over previous
#include <cuda_runtime.h>

// xg scratch: [B=32][T=2048][4H=1024] fp32 = 256 MB
__device__ float g_xg[32ull * 2048ull * 1024ull];

// ---------------- f32x2 helpers (sm_103a packed fp32) ----------------
__device__ __forceinline__ void fma2(unsigned long long &acc,
                                     unsigned long long a,
                                     unsigned long long b) {
    asm("fma.rn.f32x2 %0, %1, %2, %0;" : "+l"(acc) : "l"(a), "l"(b));
}
__device__ __forceinline__ unsigned long long splat2(float x) {
    unsigned long long r;
    unsigned xu = __float_as_uint(x);
    asm("mov.b64 %0, {%1, %1};" : "=l"(r) : "r"(xu));
    return r;
}
__device__ __forceinline__ float hadd2(unsigned long long v) {
    float lo, hi;
    asm("mov.b64 {%0, %1}, %2;" : "=f"(lo), "=f"(hi) : "l"(v));
    return lo + hi;
}
__device__ __forceinline__ float sigf(float x) {
    return __fdividef(1.f, 1.f + __expf(-x));
}
__device__ __forceinline__ float tanhf_fast(float x) {
    return __fdividef(2.f, 1.f + __expf(-2.f * x)) - 1.f;
}
__device__ __forceinline__ unsigned smem_u32(const void* p) {
    return (unsigned)__cvta_generic_to_shared(p);
}

// mbarrier primitives
__device__ __forceinline__ void mbar_init(unsigned mbar, unsigned cnt) {
    asm volatile("mbarrier.init.shared.b64 [%0], %1;" :: "r"(mbar), "r"(cnt) : "memory");
}
__device__ __forceinline__ void mbar_arm_tx(unsigned mbar, unsigned bytes) {
    asm volatile("mbarrier.arrive.expect_tx.shared.b64 _, [%0], %1;"
                 :: "r"(mbar), "r"(bytes) : "memory");
}
__device__ __forceinline__ void mbar_wait(unsigned mbar, unsigned parity) {
    unsigned done;
    asm volatile(
        "{\n\t.reg .pred p;\n\t"
        "mbarrier.try_wait.parity.acquire.cta.shared::cta.b64 p, [%1], %2;\n\t"
        "selp.b32 %0, 1, 0, p;\n\t}"
        : "=r"(done) : "r"(mbar), "r"(parity) : "memory");
    while (!done) {
        asm volatile(
            "{\n\t.reg .pred p;\n\t"
            "mbarrier.try_wait.parity.acquire.cta.shared::cta.b64 p, [%1], %2, 0x989680;\n\t"
            "selp.b32 %0, 1, 0, p;\n\t}"
            : "=r"(done) : "r"(mbar), "r"(parity) : "memory");
    }
}
// 16-byte remote store + tx-signal (data delivery IS the sync)
__device__ __forceinline__ void st_async_v4(unsigned laddr, unsigned lbar,
                                            unsigned rank, float4 v) {
    asm volatile(
        "{\n\t.reg .b32 ra, rb;\n\t"
        "mapa.shared::cluster.u32 ra, %0, %2;\n\t"
        "mapa.shared::cluster.u32 rb, %1, %2;\n\t"
        "st.async.shared::cluster.mbarrier::complete_tx::bytes.v4.b32 "
        "[ra], {%3, %4, %5, %6}, [rb];\n\t}"
        :: "r"(laddr), "r"(lbar), "r"(rank),
           "r"(__float_as_uint(v.x)), "r"(__float_as_uint(v.y)),
           "r"(__float_as_uint(v.z)), "r"(__float_as_uint(v.w)) : "memory");
}

// =====================================================================
// Phase 1: xg[m][g] = relu(x)[m][:] . W_ih[g][:] + b_ih[g] + b_hh[g]
// (unchanged — FMA-bound, not the bottleneck)
// =====================================================================
__global__ __launch_bounds__(256, 2) void p1_gemm(
    const float* __restrict__ x, const float* __restrict__ Wih,
    const float* __restrict__ bih, const float* __restrict__ bhh)
{
    __shared__ __align__(16) float Asm[16][132];  // [k][m]
    __shared__ __align__(16) float Wsm[16][132];  // [k][g]

    const int t  = threadIdx.x;
    const int tx = t & 15, ty = t >> 4;
    const int mb = blockIdx.y * 128;
    const int gb = blockIdx.x * 128;

    unsigned long long acc[4][8];
    #pragma unroll
    for (int p = 0; p < 4; p++)
        #pragma unroll
        for (int g = 0; g < 8; g++) acc[p][g] = 0ull;

    for (int kb = 0; kb < 256; kb += 16) {
        #pragma unroll
        for (int i = 0; i < 2; i++) {
            int idx = t + i * 256;
            int m   = idx >> 2;
            int kc  = (idx & 3) << 2;
            float4 av = *(const float4*)(x + (size_t)(mb + m) * 256 + kb + kc);
            Asm[kc + 0][m] = fmaxf(av.x, 0.f);
            Asm[kc + 1][m] = fmaxf(av.y, 0.f);
            Asm[kc + 2][m] = fmaxf(av.z, 0.f);
            Asm[kc + 3][m] = fmaxf(av.w, 0.f);
            float4 wv = *(const float4*)(Wih + (size_t)(gb + m) * 256 + kb + kc);
            Wsm[kc + 0][m] = wv.x;
            Wsm[kc + 1][m] = wv.y;
            Wsm[kc + 2][m] = wv.z;
            Wsm[kc + 3][m] = wv.w;
        }
        __syncthreads();
        #pragma unroll
        for (int k = 0; k < 16; k++) {
            ulonglong2 a01 = *(const ulonglong2*)&Asm[k][ty * 8];
            ulonglong2 a23 = *(const ulonglong2*)&Asm[k][ty * 8 + 4];
            float4 w0 = *(const float4*)&Wsm[k][tx * 8];
            float4 w1 = *(const float4*)&Wsm[k][tx * 8 + 4];
            float wf[8] = {w0.x, w0.y, w0.z, w0.w, w1.x, w1.y, w1.z, w1.w};
            #pragma unroll
            for (int g = 0; g < 8; g++) {
                unsigned long long ws = splat2(wf[g]);
                fma2(acc[0][g], a01.x, ws);
                fma2(acc[1][g], a01.y, ws);
                fma2(acc[2][g], a23.x, ws);
                fma2(acc[3][g], a23.y, ws);
            }
        }
        __syncthreads();
    }

    float bs[8];
    {
        const float4* bi = (const float4*)(bih + gb + tx * 8);
        const float4* bh = (const float4*)(bhh + gb + tx * 8);
        float4 b0 = bi[0], b1 = bi[1], c0 = bh[0], c1 = bh[1];
        bs[0] = b0.x + c0.x; bs[1] = b0.y + c0.y; bs[2] = b0.z + c0.z; bs[3] = b0.w + c0.w;
        bs[4] = b1.x + c1.x; bs[5] = b1.y + c1.y; bs[6] = b1.z + c1.z; bs[7] = b1.w + c1.w;
    }
    #pragma unroll
    for (int p = 0; p < 4; p++) {
        float lo[8], hi[8];
        #pragma unroll
        for (int g = 0; g < 8; g++) {
            float l, h;
            asm("mov.b64 {%0, %1}, %2;" : "=f"(l), "=f"(h) : "l"(acc[p][g]));
            lo[g] = l + bs[g];
            hi[g] = h + bs[g];
        }
        size_t m0 = (size_t)(mb + ty * 8 + 2 * p);
        float* r0 = g_xg + m0 * 1024 + gb + tx * 8;
        float* r1 = r0 + 1024;
        *(float4*)(r0)     = make_float4(lo[0], lo[1], lo[2], lo[3]);
        *(float4*)(r0 + 4) = make_float4(lo[4], lo[5], lo[6], lo[7]);
        *(float4*)(r1)     = make_float4(hi[0], hi[1], hi[2], hi[3]);
        *(float4*)(r1 + 4) = make_float4(hi[4], hi[5], hi[6], hi[7]);
    }
}

// =====================================================================
// Phase 2: recurrence (R4 chassis + split phase barriers).
// 16 clusters x 8 CTAs; cluster c handles batches {2c, 2c+1}. CTA rank
// r owns h-indices [32r,32r+32). h buffer rank-major:
// h_lin[buf][r*64 + b*32 + j].
// Barriers split by SOURCE rank group, matching the kh data split:
//   barA[ph]: signaled by ranks 0-3 (h_lin[0..256))  — waited by kh=0
//   barB[ph]: signaled by ranks 4-7 (h_lin[256..512)) — waited by kh=1
// Each group's warps start the matvec as soon as THEIR half of h has
// arrived; the __syncthreads join overlaps the other group's wire time.
// =====================================================================
__global__ __launch_bounds__(256, 1) __cluster_dims__(8, 1, 1)
void p2_lstm(const float* __restrict__ Whh, float* __restrict__ out)
{
    __shared__ __align__(16) float h_lin[2][512];     // [buf][r*64+b*32+j]
    __shared__ __align__(16) float ring[4][256];      // xg [slot][b*128+gt*32+j]
    __shared__ __align__(8)  float red_sm[2][128][2]; // [kh][row][batch]
    __shared__ __align__(8)  unsigned long long barr[4]; // A0,A1,B0,B1

    unsigned rank;
    asm("mov.u32 %0, %%cluster_ctarank;" : "=r"(rank));
    const int t   = threadIdx.x;
    const int row = t & 127;
    const int kh  = t >> 7;
    const int gt  = row >> 5;
    const int j   = row & 31;
    const int G   = gt * 256 + (int)rank * 32 + j;   // global gate row
    const int b0  = (blockIdx.x >> 3) * 2;

    // persistent weights: 64 x f32x2 in registers (k-linear over kh half)
    unsigned long long w2[64];
    {
        const unsigned long long* wp =
            (const unsigned long long*)(Whh + (size_t)G * 256 + kh * 128);
        #pragma unroll
        for (int i = 0; i < 64; i++) w2[i] = wp[i];
    }

    for (int i = t; i < 1024; i += 256) ((float*)h_lin)[i] = 0.f;

    // xg ring loader: thread t covers (b=t>>7, g2=(t>>5)&3, j2=t&31)
    const float* xg_ld = g_xg
        + (size_t)(b0 + (t >> 7)) * 2048 * 1024
        + (size_t)(((t >> 5) & 3) * 256 + (int)rank * 32 + (t & 31));
    ring[0][t] = xg_ld[0];
    ring[1][t] = xg_ld[1024];
    float pend = xg_ld[2 * 1024];

    const unsigned barA0 = smem_u32(&barr[0]);
    const unsigned barA1 = smem_u32(&barr[1]);
    const unsigned barB0 = smem_u32(&barr[2]);
    const unsigned barB1 = smem_u32(&barr[3]);
    if (t == 0) {
        mbar_init(barA0, 1); mbar_init(barA1, 1);
        mbar_init(barB0, 1); mbar_init(barB1, 1);
    }
    __syncthreads();
    asm volatile("barrier.cluster.arrive.aligned;" ::: "memory");
    asm volatile("barrier.cluster.wait.aligned;"   ::: "memory");
    if (t == 0) {            // 4 source ranks x 256B per phase word
        mbar_arm_tx(barA0, 1024); mbar_arm_tx(barA1, 1024);
        mbar_arm_tx(barB0, 1024); mbar_arm_tx(barB1, 1024);
    }

    const int ub = t >> 5, uj = t & 31;              // update mapping (t<64)
    float c_state = 0.f;
    unsigned ph0 = 0, ph1 = 0;                       // my group's parities
    const unsigned mybar0 = kh ? barB0 : barA0;      // wait targets
    const unsigned mybar1 = kh ? barB1 : barA1;
    // senders signal the barrier of THEIR rank group at each destination
    const unsigned sbar0 = (rank < 4) ? barA0 : barB0;
    const unsigned sbar1 = (rank < 4) ? barA1 : barB1;
    float* out_p = out + (size_t)(b0 + ub) * 2048 * 256 + (int)rank * 32 + uj;

    for (int step = 0; step < 2048; step++) {
        const int rb = step & 1;
        const int wb = rb ^ 1;

        if (step > 0) {
            // each kh-group waits only for ITS source ranks' data;
            // re-arm done by one thread per group (t==0 for A, t==128 for B)
            if (rb) {
                mbar_wait(mybar1, ph1); ph1 ^= 1;
                if ((t & 127) == 0) mbar_arm_tx(mybar1, 1024);
            } else {
                mbar_wait(mybar0, ph0); ph0 ^= 1;
                if ((t & 127) == 0) mbar_arm_tx(mybar0, 1024);
            }
        }

        // xg pipeline: store step+2's data (loaded last iter), load step+3
        ring[(step + 2) & 3][t] = pend;
        {
            int ps = step + 3; if (ps > 2047) ps = 2047;
            pend = xg_ld[(size_t)ps * 1024];
        }

        // ---- matvec: 2 batches x 128-k half, rank-major chunks ----
        unsigned long long a0a = 0ull, a0b = 0ull, a1a = 0ull, a1b = 0ull;
        #pragma unroll
        for (int c = 0; c < 4; c++) {
            const ulonglong2* hp0 =
                (const ulonglong2*)&h_lin[rb][(kh * 4 + c) * 64];
            const ulonglong2* hp1 =
                (const ulonglong2*)&h_lin[rb][(kh * 4 + c) * 64 + 32];
            #pragma unroll
            for (int q = 0; q < 8; q++) {
                ulonglong2 hv0 = hp0[q];
                ulonglong2 hv1 = hp1[q];
                int wi = c * 16 + 2 * q;
                fma2(a0a, w2[wi],     hv0.x);
                fma2(a0b, w2[wi + 1], hv0.y);
                fma2(a1a, w2[wi],     hv1.x);
                fma2(a1b, w2[wi + 1], hv1.y);
            }
        }
        red_sm[kh][row][0] = hadd2(a0a) + hadd2(a0b);
        red_sm[kh][row][1] = hadd2(a1a) + hadd2(a1b);
        __syncthreads();   // orders h_lin[rb] reads + red/ring writes

        // ---- fused activation + c/h update (64 threads, 2 full warps) ----
        if (t < 64) {
            const float* xr = &ring[step & 3][ub * 128 + uj];
            float gi = red_sm[0][      uj][ub] + red_sm[1][      uj][ub] + xr[0];
            float gf = red_sm[0][ 32 + uj][ub] + red_sm[1][ 32 + uj][ub] + xr[32];
            float gg = red_sm[0][ 64 + uj][ub] + red_sm[1][ 64 + uj][ub] + xr[64];
            float go = red_sm[0][ 96 + uj][ub] + red_sm[1][ 96 + uj][ub] + xr[96];
            float iv = sigf(gi);
            float fv = sigf(gf);
            float gv = tanhf_fast(gg);
            float ov = sigf(go);
            c_state = fv * c_state + iv * gv;
            float h = ov * tanhf_fast(c_state);

            // gather 4 consecutive h into lanes with uj%4==0 (warp-level)
            float4 hv;
            hv.x = h;
            hv.y = __shfl_down_sync(0xffffffffu, h, 1);
            hv.z = __shfl_down_sync(0xffffffffu, h, 2);
            hv.w = __shfl_down_sync(0xffffffffu, h, 3);

            if (step < 2047 && (uj & 3) == 0) {
                unsigned laddr = smem_u32(
                    &h_lin[wb][(int)rank * 64 + ub * 32 + (uj & ~3)]);
                unsigned lbar  = wb ? sbar1 : sbar0;
                #pragma unroll
                for (int r = 0; r < 8; r++) st_async_v4(laddr, lbar, r, hv);
            }
            out_p[(size_t)step * 256] = h;
        }
    }

    asm volatile("barrier.cluster.arrive.aligned;" ::: "memory");
    asm volatile("barrier.cluster.wait.aligned;"   ::: "memory");
}

// =====================================================================
extern "C" void kernel_launch(void* const* d_in, const int* in_sizes, int n_in,
                              void* d_out, int out_size) {
    (void)in_sizes; (void)n_in; (void)out_size;
    const float* x   = (const float*)d_in[0];
    const float* Wih = (const float*)d_in[1];
    const float* Whh = (const float*)d_in[2];
    const float* bih = (const float*)d_in[3];
    const float* bhh = (const float*)d_in[4];
    float* out = (float*)d_out;

    dim3 g1(8, 512);
    p1_gemm<<<g1, 256>>>(x, Wih, bih, bhh);
    p2_lstm<<<128, 256>>>(Whh, out);   // 16 clusters of 8 CTAs
}